// round 12
// baseline (speedup 1.0000x reference)
#include <cuda_runtime.h>

#define BB 64
#define TT 256
#define HH 128
#define H4 512
#define HT 128   // t-half handled per CTA
#define HZ 256   // z-half handled per CTA
#define L2E 1.4426950408889634f

// Precomputed enc_proj = enc_output @ W1, [B*T, H]  (8 MB scratch)
__device__ float g_ep[BB * TT * HH];

// ---------------- fast-but-accurate transcendentals (err ~5e-7 abs) --------
__device__ __forceinline__ float ex2f_(float x) {
    float y; asm("ex2.approx.ftz.f32 %0, %1;" : "=f"(y) : "f"(x)); return y;
}
__device__ __forceinline__ float rcpf_(float x) {
    float y; asm("rcp.approx.ftz.f32 %0, %1;" : "=f"(y) : "f"(x)); return y;
}
__device__ __forceinline__ float tanh_(float x) {
    float ax = fabsf(x);
    float e  = ex2f_(ax * 2.8853900817779268f);   // 2*log2(e)
    float y  = fmaf(-2.0f, rcpf_(e + 1.0f), 1.0f);
    return copysignf(y, x);
}
__device__ __forceinline__ float sigm_(float x) {
    return rcpf_(1.0f + ex2f_(-L2E * x));
}

// ---------------- DSMEM / mbarrier helpers ---------------------------------
__device__ __forceinline__ unsigned smem_u32(const void* p) {
    unsigned a;
    asm("{ .reg .u64 t; cvta.to.shared.u64 t, %1; cvt.u32.u64 %0, t; }"
        : "=r"(a) : "l"(p));
    return a;
}
__device__ __forceinline__ unsigned mapa_u32(unsigned a, unsigned rank) {
    unsigned o; asm("mapa.shared::cluster.u32 %0, %1, %2;" : "=r"(o) : "r"(a), "r"(rank));
    return o;
}
__device__ __forceinline__ void st_rem_f32(unsigned a, float v) {
    asm volatile("st.shared::cluster.f32 [%0], %1;" :: "r"(a), "f"(v) : "memory");
}
__device__ __forceinline__ void st_rem_v4(unsigned a, float4 v) {
    asm volatile("st.shared::cluster.v4.f32 [%0], {%1, %2, %3, %4};"
                 :: "r"(a), "f"(v.x), "f"(v.y), "f"(v.z), "f"(v.w) : "memory");
}
__device__ __forceinline__ void mbar_init(unsigned a, unsigned cnt) {
    asm volatile("mbarrier.init.shared.b64 [%0], %1;" :: "r"(a), "r"(cnt) : "memory");
}
__device__ __forceinline__ void mbar_arrive_remote(unsigned a) {
    asm volatile("mbarrier.arrive.release.cluster.shared::cluster.b64 _, [%0];"
                 :: "r"(a) : "memory");
}
__device__ __forceinline__ void mbar_wait_parity(unsigned a, unsigned par) {
    unsigned done;
    do {
        asm volatile(
            "{ .reg .pred p;\n\t"
            "mbarrier.try_wait.parity.acquire.cluster.shared::cta.b64 p, [%1], %2, 0x989680;\n\t"
            "selp.b32 %0, 1, 0, p; }"
            : "=r"(done) : "r"(a), "r"(par) : "memory");
    } while (!done);
}
__device__ __forceinline__ void bar_sync_(int id, int cnt) {
    asm volatile("bar.sync %0, %1;" :: "r"(id), "r"(cnt) : "memory");
}
#define CLUSTER_SYNC_() do { \
    asm volatile("barrier.cluster.arrive.aligned;" ::: "memory"); \
    asm volatile("barrier.cluster.wait.aligned;"   ::: "memory"); \
} while (0)

// ---------------- kernel 1: enc_proj = enc_output @ W1 ---------------------
__global__ void __launch_bounds__(128) encproj_k(const float* __restrict__ enc,
                                                 const float* __restrict__ W1) {
    extern __shared__ float sm[];
    float* W1s = sm;                 // 128*128
    float* rb  = sm + HH * HH;       // 32*128
    int base = blockIdx.x * 32;
    {
        const float4* s4 = (const float4*)W1;
        float4* d4 = (float4*)W1s;
        for (int i = threadIdx.x; i < HH * HH / 4; i += 128) d4[i] = s4[i];
        const float4* r4 = (const float4*)(enc + (size_t)base * HH);
        float4* rd = (float4*)rb;
        for (int i = threadIdx.x; i < 32 * HH / 4; i += 128) rd[i] = r4[i];
    }
    __syncthreads();
    int j = threadIdx.x;
    for (int r0 = 0; r0 < 32; r0 += 8) {
        float acc[8] = {0.f, 0.f, 0.f, 0.f, 0.f, 0.f, 0.f, 0.f};
        #pragma unroll 8
        for (int k = 0; k < HH; ++k) {
            float w = W1s[k * HH + j];
            #pragma unroll
            for (int rr = 0; rr < 8; ++rr)
                acc[rr] = fmaf(rb[(r0 + rr) * HH + k], w, acc[rr]);
        }
        #pragma unroll
        for (int rr = 0; rr < 8; ++rr)
            g_ep[(size_t)(base + r0 + rr) * HH + j] = acc[rr];
    }
}

// ---------------- kernel 2: 2-CTA-cluster decoder --------------------------
struct DecodeSmem {
    unsigned long long mb_z;     // z-base halves ready (64 remote arrives/phase)
    unsigned long long mb_s;     // peer's E-triple ready (1 arrive/phase)
    float ep[HT * HH];    // 64 KB: this CTA's t-half of enc_proj
    float W2s[HH * HH];   // 64 KB
    float Wks[2 * H4];    //  4 KB
    float bs[H4];
    float Vs[HH];
    float xs[TT * 2];
    float hs[HH];
    float cs[HH];
    float zp[8 * HZ];     //  8 KB: k-partials for this CTA's z-half
    float zs[2][H4];      //  double-buffered z-base (h@Wr + b), both halves
    float ap[4 * HH];     //  C k-quarter partials
    float redv[16];       //  per-warp score triples
    int   redi[16];
    float redsum[16];
    float exch[2][4];     //  peer writes (m, idx-bits, S) here, by parity
};

__global__ void __launch_bounds__(512, 1) __cluster_dims__(2, 1, 1)
decode_k(const float* __restrict__ x,   const float* __restrict__ h0,
         const float* __restrict__ c0,  const float* __restrict__ W2,
         const float* __restrict__ V,   const float* __restrict__ Wk,
         const float* __restrict__ Wr,  const float* __restrict__ bias,
         float* __restrict__ out)
{
    extern __shared__ float smraw[];
    DecodeSmem* s = (DecodeSmem*)smraw;

    const int b    = blockIdx.x >> 1;
    unsigned rank; asm("mov.u32 %0, %%cluster_ctarank;" : "=r"(rank));
    const unsigned peer = rank ^ 1u;
    const int tid  = threadIdx.x;
    const int lane = tid & 31;
    const int warp = tid >> 5;

    // ---- prologue: stage reusable data into SMEM ---------------------------
    {
        const float4* epsrc = (const float4*)(g_ep + ((size_t)b * TT + rank * HT) * HH);
        float4* epdst = (float4*)s->ep;
        for (int i = tid; i < HT * HH / 4; i += 512) epdst[i] = epsrc[i];

        const float4* w2src = (const float4*)W2;
        float4* w2dst = (float4*)s->W2s;
        for (int i = tid; i < HH * HH / 4; i += 512) w2dst[i] = w2src[i];

        if (tid < 2 * H4 / 4) ((float4*)s->Wks)[tid] = ((const float4*)Wk)[tid];
        if (tid < H4 / 4)     ((float4*)s->bs)[tid]  = ((const float4*)bias)[tid];
        if (tid < HH / 4)     ((float4*)s->Vs)[tid]  = ((const float4*)V)[tid];
        if (tid < TT * 2 / 4) ((float4*)s->xs)[tid]  = ((const float4*)(x + (size_t)b * TT * 2))[tid];
        if (tid < HH / 4)     ((float4*)s->hs)[tid]  = ((const float4*)(h0 + (size_t)b * HH))[tid];
        if (tid < HH / 4)     ((float4*)s->cs)[tid]  = ((const float4*)(c0 + (size_t)b * HH))[tid];
        if (tid == 0) {
            mbar_init(smem_u32(&s->mb_z), 64);   // 64 v4 remote arrives per phase
            mbar_init(smem_u32(&s->mb_s), 1);    // 1 triple arrive per phase
        }
    }
    __syncthreads();
    CLUSTER_SYNC_();   // peer barriers initialized before any remote arrive

    const unsigned mbz_local = smem_u32(&s->mb_z);
    const unsigned mbs_local = smem_u32(&s->mb_s);
    const unsigned mbz_rem   = mapa_u32(mbz_local, peer);
    const unsigned mbs_rem   = mapa_u32(mbs_local, peer);
    const unsigned zs0_base  = smem_u32(s->zs[0]);
    const unsigned zs1_base  = smem_u32(s->zs[1]);
    const unsigned ex_rem0   = mapa_u32(smem_u32(s->exch[0]), peer);
    const unsigned ex_rem1   = mapa_u32(smem_u32(s->exch[1]), peer);

    const float4 Vr = ((const float4*)s->Vs)[lane];

    // A-role layout: kq = k-eighth (0..7), j4 = output quad within our z-half
    const int kq = tid >> 6;
    const int j4 = tid & 63;
    const float* WrB = Wr + (size_t)kq * 16 * H4 + rank * HZ + j4 * 4;

    // per-thread pointer state (registers; consumed only by warps 0-3)
    float p0 = 1.0f, p1 = 1.0f;

    // ---- prologue: zp_0 from h0, then reduce+exchange z-base (parity 0) ----
    {
        const float* hp = s->hs + kq * 16;
        const float* wp = WrB;
        float4 az = make_float4(0.f, 0.f, 0.f, 0.f);
        #pragma unroll
        for (int k = 0; k < 16; ++k) {
            float hk = hp[k];
            float4 w = *(const float4*)wp;
            wp += H4;
            az.x = fmaf(hk, w.x, az.x);
            az.y = fmaf(hk, w.y, az.y);
            az.z = fmaf(hk, w.z, az.z);
            az.w = fmaf(hk, w.w, az.w);
        }
        ((float4*)(s->zp + kq * HZ))[j4] = az;
    }
    __syncthreads();
    if (tid < HZ) {
        int jg = rank * HZ + tid;
        float zj = s->zp[tid]          + s->zp[HZ + tid]
                 + s->zp[2 * HZ + tid] + s->zp[3 * HZ + tid]
                 + s->zp[4 * HZ + tid] + s->zp[5 * HZ + tid]
                 + s->zp[6 * HZ + tid] + s->zp[7 * HZ + tid];
        zj += s->bs[jg];
        s->zs[0][jg] = zj;
        float z1 = __shfl_down_sync(0xffffffffu, zj, 1);
        float z2 = __shfl_down_sync(0xffffffffu, zj, 2);
        float z3 = __shfl_down_sync(0xffffffffu, zj, 3);
        if ((lane & 3) == 0) {
            st_rem_v4(mapa_u32(zs0_base + 4u * jg, peer),
                      make_float4(zj, z1, z2, z3));
            mbar_arrive_remote(mbz_rem);
        }
    }
    __syncthreads();

    for (int i = 0; i < TT; ++i) {
        const unsigned par = i & 1u;
        const unsigned nxt = par ^ 1u;

        // ---- B: wait z-base halves; add ptr@Wk (reg ptr); LSTM gates --------
        mbar_wait_parity(mbz_local, par);   // peer half (arrived ~1 iter ago)
        if (tid < HH) {
            const float* zb = s->zs[par];
            float zi = zb[tid];
            float zf = zb[HH + tid];
            float zg = zb[2 * HH + tid];
            float zo = zb[3 * HH + tid];
            zi = fmaf(p0, s->Wks[tid],          fmaf(p1, s->Wks[H4 + tid],          zi));
            zf = fmaf(p0, s->Wks[HH + tid],     fmaf(p1, s->Wks[H4 + HH + tid],     zf));
            zg = fmaf(p0, s->Wks[2 * HH + tid], fmaf(p1, s->Wks[H4 + 2 * HH + tid], zg));
            zo = fmaf(p0, s->Wks[3 * HH + tid], fmaf(p1, s->Wks[H4 + 3 * HH + tid], zo));
            float ig = sigm_(zi);
            float fg = sigm_(zf);
            float gg = tanh_(zg);
            float og = sigm_(zo);
            float cn = fmaf(fg, s->cs[tid], ig * gg);
            s->cs[tid] = cn;
            s->hs[tid] = og * tanh_(cn);
        }
        __syncthreads();                              // b1: hs visible

        // ---- C: a-partials = h @ W2 (4 independent accumulators) -----------
        {
            const int q = tid >> 7, j = tid & 127;
            const float* w2 = s->W2s + q * 32 * HH + j;
            const float* hp = s->hs + q * 32;
            float a0 = 0.f, a1 = 0.f, a2 = 0.f, a3 = 0.f;
            #pragma unroll
            for (int k = 0; k < 32; k += 4) {
                a0 = fmaf(hp[k],     w2[k * HH],       a0);
                a1 = fmaf(hp[k + 1], w2[(k + 1) * HH], a1);
                a2 = fmaf(hp[k + 2], w2[(k + 2) * HH], a2);
                a3 = fmaf(hp[k + 3], w2[(k + 3) * HH], a3);
            }
            s->ap[q * HH + j] = (a0 + a1) + (a2 + a3);
        }
        __syncthreads();                              // b2: ap visible

        // ---- D fused with A(i+1): scores kept in registers, running triple -
        float vmax = -3.4e38f, ssum = 0.f, e_mine = 0.f;
        int   imax = 0;
        {
            // fold the 4 k-quarter partials into this lane's a-quad
            const float4* apq = (const float4*)s->ap;
            float4 q0 = apq[lane], q1 = apq[32 + lane],
                   q2 = apq[64 + lane], q3 = apq[96 + lane];
            float4 a4;
            a4.x = (q0.x + q1.x) + (q2.x + q3.x);
            a4.y = (q0.y + q1.y) + (q2.y + q3.y);
            a4.z = (q0.z + q1.z) + (q2.z + q3.z);
            a4.w = (q0.w + q1.w) + (q2.w + q3.w);

            // h_i slice via 4 vector loads
            const float4* h4 = ((const float4*)s->hs) + kq * 4;
            float4 hv0 = h4[0], hv1 = h4[1], hv2 = h4[2], hv3 = h4[3];
            float hreg[16] = {hv0.x, hv0.y, hv0.z, hv0.w,
                              hv1.x, hv1.y, hv1.z, hv1.w,
                              hv2.x, hv2.y, hv2.z, hv2.w,
                              hv3.x, hv3.y, hv3.z, hv3.w};
            float4 buf[8];
            #pragma unroll
            for (int k = 0; k < 8; ++k)
                buf[k] = *(const float4*)(WrB + (size_t)k * H4);
            float4 az = make_float4(0.f, 0.f, 0.f, 0.f);
            #pragma unroll
            for (int it = 0; it < 8; ++it) {
                float4 wN = *(const float4*)(WrB + (size_t)(8 + it) * H4);
                az.x = fmaf(hreg[it], buf[it].x, az.x);
                az.y = fmaf(hreg[it], buf[it].y, az.y);
                az.z = fmaf(hreg[it], buf[it].z, az.z);
                az.w = fmaf(hreg[it], buf[it].w, az.w);
                int tl = warp + it * 16;
                float4 p = ((const float4*)(s->ep + tl * HH))[lane];
                float sv;
                sv = Vr.x * tanh_(p.x + a4.x);
                sv = fmaf(Vr.y, tanh_(p.y + a4.y), sv);
                sv = fmaf(Vr.z, tanh_(p.z + a4.z), sv);
                sv = fmaf(Vr.w, tanh_(p.w + a4.w), sv);
                sv += __shfl_xor_sync(0xffffffffu, sv, 16);
                sv += __shfl_xor_sync(0xffffffffu, sv, 8);
                sv += __shfl_xor_sync(0xffffffffu, sv, 4);
                sv += __shfl_xor_sync(0xffffffffu, sv, 2);
                sv += __shfl_xor_sync(0xffffffffu, sv, 1);
                // butterfly leaves sv in ALL lanes -> fold into running triple
                float e = ex2f_(sv * L2E);            // raw exp2 (|v| small)
                ssum += e;
                if (sv > vmax) { vmax = sv; imax = (int)rank * HT + tl; }
                if (lane == it) e_mine = e;           // kept for output store
                az.x = fmaf(hreg[8 + it], wN.x, az.x);
                az.y = fmaf(hreg[8 + it], wN.y, az.y);
                az.z = fmaf(hreg[8 + it], wN.z, az.z);
                az.w = fmaf(hreg[8 + it], wN.w, az.w);
            }
            ((float4*)(s->zp + kq * HZ))[j4] = az;   // z partials for step i+1
            if (lane == 0) {                          // per-warp triple
                s->redv[warp] = vmax; s->redi[warp] = imax; s->redsum[warp] = ssum;
            }
        }
        __syncthreads();                              // b3: zp + red visible

        // ---- tid0: scan 16 triples, send to peer (overlaps A2') -------------
        if (tid == 0) {
            float m_r = s->redv[0]; int i_r = s->redi[0];
            float S_r = 0.f;
            #pragma unroll
            for (int w16 = 0; w16 < 16; ++w16) S_r += s->redsum[w16];
            #pragma unroll
            for (int w16 = 1; w16 < 16; ++w16) {
                float rv = s->redv[w16]; int ri = s->redi[w16];
                if (rv > m_r || (rv == m_r && ri < i_r)) { m_r = rv; i_r = ri; }
            }
            unsigned exr = par ? ex_rem1 : ex_rem0;
            st_rem_f32(exr + 0u, m_r);
            st_rem_f32(exr + 4u, __int_as_float(i_r));
            st_rem_f32(exr + 8u, S_r);
            mbar_arrive_remote(mbs_rem);
        }

        // ---- A2' (warps 4-11): reduce zp_{i+1} + b; exchange z-base ---------
        if (warp >= 4 && warp < 12) {
            int zt = tid - 128;                       // 0..255
            int jg = rank * HZ + zt;
            float zj = s->zp[zt]          + s->zp[HZ + zt]
                     + s->zp[2 * HZ + zt] + s->zp[3 * HZ + zt]
                     + s->zp[4 * HZ + zt] + s->zp[5 * HZ + zt]
                     + s->zp[6 * HZ + zt] + s->zp[7 * HZ + zt];
            zj += s->bs[jg];
            s->zs[nxt][jg] = zj;
            float z1 = __shfl_down_sync(0xffffffffu, zj, 1);
            float z2 = __shfl_down_sync(0xffffffffu, zj, 2);
            float z3 = __shfl_down_sync(0xffffffffu, zj, 3);
            if ((lane & 3) == 0) {
                unsigned zb = (nxt ? zs1_base : zs0_base) + 4u * jg;
                st_rem_v4(mapa_u32(zb, peer), make_float4(zj, z1, z2, z3));
                mbar_arrive_remote(mbz_rem);
            }
        }
        if (warp < 12) bar_sync_(7, 384);             // zs[nxt] -> warps 0-3

        // ---- combine (ALL warps, redundant): gi/kE0 in regs; write output ---
        {
            mbar_wait_parity(mbs_local, par);         // peer triple landed
            float m_r = s->redv[0]; int i_r = s->redi[0];
            float S_r = 0.f;
            #pragma unroll
            for (int w16 = 0; w16 < 16; ++w16) S_r += s->redsum[w16];
            #pragma unroll
            for (int w16 = 1; w16 < 16; ++w16) {
                float rv = s->redv[w16]; int ri = s->redi[w16];
                if (rv > m_r || (rv == m_r && ri < i_r)) { m_r = rv; i_r = ri; }
            }
            const float* ex = s->exch[par];
            float pm = ex[0];
            int   pi = __float_as_int(ex[1]);
            float pS = ex[2];
            bool  tp = (pm > m_r) || (pm == m_r && pi < i_r);
            int   gi = tp ? pi : i_r;
            float St = S_r + pS;
            float kE0 = rcpf_(St);
            kE0 = kE0 * (2.0f - St * kE0);            // NR step -> full fp32 acc
            p0 = s->xs[gi * 2];
            p1 = s->xs[gi * 2 + 1];
            if (lane < 8)                              // each warp: its 8 rows
                out[((size_t)b * TT + i) * TT + rank * HT + warp + lane * 16]
                    = e_mine * kE0;
        }
        // WAR safety: red written at end of D_{i+1} only after b1_{i+1},
        // which requires all warps past combine_i; zs/exch double-buffered
        // by parity with the send->peer-combine->peer-b1 transitive chain;
        // zp gated by b2/b3 as before. Warps 12-15 skip A2'/bar7 but join
        // b1/b2/b3 and combine (they store output rows).
    }
    CLUSTER_SYNC_();   // keep SMEM alive until peer's remote ops are done
}

// ---------------- launch ----------------------------------------------------
extern "C" void kernel_launch(void* const* d_in, const int* in_sizes, int n_in,
                              void* d_out, int out_size) {
    const float* x   = (const float*)d_in[0];
    const float* enc = (const float*)d_in[1];
    const float* h0  = (const float*)d_in[2];
    const float* c0  = (const float*)d_in[3];
    const float* W1  = (const float*)d_in[4];
    const float* W2  = (const float*)d_in[5];
    const float* V   = (const float*)d_in[6];
    const float* Wk  = (const float*)d_in[7];
    const float* Wr  = (const float*)d_in[8];
    const float* bia = (const float*)d_in[9];
    float* out = (float*)d_out;

    const int enc_smem = (HH * HH + 32 * HH) * (int)sizeof(float);  // 80 KB
    cudaFuncSetAttribute(encproj_k, cudaFuncAttributeMaxDynamicSharedMemorySize,
                         enc_smem);
    cudaFuncSetAttribute(decode_k, cudaFuncAttributeMaxDynamicSharedMemorySize,
                         (int)sizeof(DecodeSmem));

    encproj_k<<<(BB * TT) / 32, 128, enc_smem>>>(enc, W1);
    decode_k<<<BB * 2, 512, sizeof(DecodeSmem)>>>(x, h0, c0, W2, V, Wk, Wr, bia, out);
}

// round 13
// speedup vs baseline: 1.0860x; 1.0860x over previous
#include <cuda_runtime.h>

#define BB 64
#define TT 256
#define HH 128
#define H4 512
#define HT 128   // t-half handled per CTA
#define HZ 256   // z-half handled per CTA
#define L2E 1.4426950408889634f

// Precomputed enc_proj = enc_output @ W1, [B*T, H]  (8 MB scratch)
__device__ float g_ep[BB * TT * HH];

// ---------------- fast-but-accurate transcendentals (err ~5e-7 abs) --------
__device__ __forceinline__ float ex2f_(float x) {
    float y; asm("ex2.approx.ftz.f32 %0, %1;" : "=f"(y) : "f"(x)); return y;
}
__device__ __forceinline__ float rcpf_(float x) {
    float y; asm("rcp.approx.ftz.f32 %0, %1;" : "=f"(y) : "f"(x)); return y;
}
__device__ __forceinline__ float tanh_(float x) {
    float ax = fabsf(x);
    float e  = ex2f_(ax * 2.8853900817779268f);   // 2*log2(e)
    float y  = fmaf(-2.0f, rcpf_(e + 1.0f), 1.0f);
    return copysignf(y, x);
}
__device__ __forceinline__ float sigm_(float x) {
    return rcpf_(1.0f + ex2f_(-L2E * x));
}

// ---------------- DSMEM / mbarrier helpers ---------------------------------
__device__ __forceinline__ unsigned smem_u32(const void* p) {
    unsigned a;
    asm("{ .reg .u64 t; cvta.to.shared.u64 t, %1; cvt.u32.u64 %0, t; }"
        : "=r"(a) : "l"(p));
    return a;
}
__device__ __forceinline__ unsigned mapa_u32(unsigned a, unsigned rank) {
    unsigned o; asm("mapa.shared::cluster.u32 %0, %1, %2;" : "=r"(o) : "r"(a), "r"(rank));
    return o;
}
__device__ __forceinline__ void st_rem_f32(unsigned a, float v) {
    asm volatile("st.shared::cluster.f32 [%0], %1;" :: "r"(a), "f"(v) : "memory");
}
__device__ __forceinline__ void st_rem_v4(unsigned a, float4 v) {
    asm volatile("st.shared::cluster.v4.f32 [%0], {%1, %2, %3, %4};"
                 :: "r"(a), "f"(v.x), "f"(v.y), "f"(v.z), "f"(v.w) : "memory");
}
__device__ __forceinline__ void mbar_init(unsigned a, unsigned cnt) {
    asm volatile("mbarrier.init.shared.b64 [%0], %1;" :: "r"(a), "r"(cnt) : "memory");
}
__device__ __forceinline__ void mbar_arrive_remote(unsigned a) {
    asm volatile("mbarrier.arrive.release.cluster.shared::cluster.b64 _, [%0];"
                 :: "r"(a) : "memory");
}
__device__ __forceinline__ void mbar_wait_parity(unsigned a, unsigned par) {
    unsigned done;
    do {
        asm volatile(
            "{ .reg .pred p;\n\t"
            "mbarrier.try_wait.parity.acquire.cluster.shared::cta.b64 p, [%1], %2, 0x989680;\n\t"
            "selp.b32 %0, 1, 0, p; }"
            : "=r"(done) : "r"(a), "r"(par) : "memory");
    } while (!done);
}
__device__ __forceinline__ void bar_sync_(int id, int cnt) {
    asm volatile("bar.sync %0, %1;" :: "r"(id), "r"(cnt) : "memory");
}
#define CLUSTER_SYNC_() do { \
    asm volatile("barrier.cluster.arrive.aligned;" ::: "memory"); \
    asm volatile("barrier.cluster.wait.aligned;"   ::: "memory"); \
} while (0)

// ---------------- kernel 1: enc_proj = enc_output @ W1 ---------------------
__global__ void __launch_bounds__(128) encproj_k(const float* __restrict__ enc,
                                                 const float* __restrict__ W1) {
    extern __shared__ float sm[];
    float* W1s = sm;                 // 128*128
    float* rb  = sm + HH * HH;       // 32*128
    int base = blockIdx.x * 32;
    {
        const float4* s4 = (const float4*)W1;
        float4* d4 = (float4*)W1s;
        for (int i = threadIdx.x; i < HH * HH / 4; i += 128) d4[i] = s4[i];
        const float4* r4 = (const float4*)(enc + (size_t)base * HH);
        float4* rd = (float4*)rb;
        for (int i = threadIdx.x; i < 32 * HH / 4; i += 128) rd[i] = r4[i];
    }
    __syncthreads();
    int j = threadIdx.x;
    for (int r0 = 0; r0 < 32; r0 += 8) {
        float acc[8] = {0.f, 0.f, 0.f, 0.f, 0.f, 0.f, 0.f, 0.f};
        #pragma unroll 8
        for (int k = 0; k < HH; ++k) {
            float w = W1s[k * HH + j];
            #pragma unroll
            for (int rr = 0; rr < 8; ++rr)
                acc[rr] = fmaf(rb[(r0 + rr) * HH + k], w, acc[rr]);
        }
        #pragma unroll
        for (int rr = 0; rr < 8; ++rr)
            g_ep[(size_t)(base + r0 + rr) * HH + j] = acc[rr];
    }
}

// ---------------- kernel 2: 2-CTA-cluster decoder --------------------------
struct DecodeSmem {
    unsigned long long mb_z;     // z-base halves ready (64 remote arrives/phase)
    unsigned long long mb_s;     // peer's E-triple ready (1 arrive/phase)
    float ep[HT * HH];    // 64 KB: this CTA's t-half of enc_proj
    float W2s[HH * HH];   // 64 KB
    float Wks[2 * H4];    //  4 KB
    float bs[H4];
    float Vs[HH];
    float xs[TT * 2];
    float hs[HH];
    float cs[HH];
    float zp[8 * HZ];     //  8 KB: k-partials for this CTA's z-half
    float zs[2][H4];      //  double-buffered z-base (h@Wr + b), both halves
    float ap[4 * HH];     //  C k-quarter partials
    float sc[HT];         //  our half of the scores only
    float exch[2][4];     //  peer writes (m, idx-bits, S) here, by parity
    float pbuf[2];        //  ptr broadcast (written by warp 0 lane 0)
};

__global__ void __launch_bounds__(512, 1) __cluster_dims__(2, 1, 1)
decode_k(const float* __restrict__ x,   const float* __restrict__ h0,
         const float* __restrict__ c0,  const float* __restrict__ W2,
         const float* __restrict__ V,   const float* __restrict__ Wk,
         const float* __restrict__ Wr,  const float* __restrict__ bias,
         float* __restrict__ out)
{
    extern __shared__ float smraw[];
    DecodeSmem* s = (DecodeSmem*)smraw;

    const int b    = blockIdx.x >> 1;
    unsigned rank; asm("mov.u32 %0, %%cluster_ctarank;" : "=r"(rank));
    const unsigned peer = rank ^ 1u;
    const int tid  = threadIdx.x;
    const int lane = tid & 31;
    const int warp = tid >> 5;

    // ---- prologue: stage reusable data into SMEM ---------------------------
    {
        const float4* epsrc = (const float4*)(g_ep + ((size_t)b * TT + rank * HT) * HH);
        float4* epdst = (float4*)s->ep;
        for (int i = tid; i < HT * HH / 4; i += 512) epdst[i] = epsrc[i];

        const float4* w2src = (const float4*)W2;
        float4* w2dst = (float4*)s->W2s;
        for (int i = tid; i < HH * HH / 4; i += 512) w2dst[i] = w2src[i];

        if (tid < 2 * H4 / 4) ((float4*)s->Wks)[tid] = ((const float4*)Wk)[tid];
        if (tid < H4 / 4)     ((float4*)s->bs)[tid]  = ((const float4*)bias)[tid];
        if (tid < HH / 4)     ((float4*)s->Vs)[tid]  = ((const float4*)V)[tid];
        if (tid < TT * 2 / 4) ((float4*)s->xs)[tid]  = ((const float4*)(x + (size_t)b * TT * 2))[tid];
        if (tid < HH / 4)     ((float4*)s->hs)[tid]  = ((const float4*)(h0 + (size_t)b * HH))[tid];
        if (tid < HH / 4)     ((float4*)s->cs)[tid]  = ((const float4*)(c0 + (size_t)b * HH))[tid];
        if (tid == 0) {
            s->pbuf[0] = 1.0f; s->pbuf[1] = 1.0f;
            mbar_init(smem_u32(&s->mb_z), 64);   // 64 v4 remote arrives per phase
            mbar_init(smem_u32(&s->mb_s), 1);    // 1 triple arrive per phase
        }
    }
    __syncthreads();
    CLUSTER_SYNC_();   // peer barriers initialized before any remote arrive

    const unsigned mbz_local = smem_u32(&s->mb_z);
    const unsigned mbs_local = smem_u32(&s->mb_s);
    const unsigned mbz_rem   = mapa_u32(mbz_local, peer);
    const unsigned mbs_rem   = mapa_u32(mbs_local, peer);
    const unsigned zs0_base  = smem_u32(s->zs[0]);
    const unsigned zs1_base  = smem_u32(s->zs[1]);
    const unsigned ex_rem0   = mapa_u32(smem_u32(s->exch[0]), peer);
    const unsigned ex_rem1   = mapa_u32(smem_u32(s->exch[1]), peer);

    const float4 Vr = ((const float4*)s->Vs)[lane];

    // A-role layout: kq = k-eighth (0..7), j4 = output quad within our z-half
    const int kq = tid >> 6;
    const int j4 = tid & 63;
    const float* WrB = Wr + (size_t)kq * 16 * H4 + rank * HZ + j4 * 4;

    // ---- prologue: zp_0 from h0, then reduce+exchange z-base (parity 0) ----
    {
        const float* hp = s->hs + kq * 16;
        const float* wp = WrB;
        float4 az = make_float4(0.f, 0.f, 0.f, 0.f);
        #pragma unroll
        for (int k = 0; k < 16; ++k) {
            float hk = hp[k];
            float4 w = *(const float4*)wp;
            wp += H4;
            az.x = fmaf(hk, w.x, az.x);
            az.y = fmaf(hk, w.y, az.y);
            az.z = fmaf(hk, w.z, az.z);
            az.w = fmaf(hk, w.w, az.w);
        }
        ((float4*)(s->zp + kq * HZ))[j4] = az;
    }
    __syncthreads();
    if (tid < HZ) {
        int jg = rank * HZ + tid;
        float zj = s->zp[tid]          + s->zp[HZ + tid]
                 + s->zp[2 * HZ + tid] + s->zp[3 * HZ + tid]
                 + s->zp[4 * HZ + tid] + s->zp[5 * HZ + tid]
                 + s->zp[6 * HZ + tid] + s->zp[7 * HZ + tid];
        zj += s->bs[jg];
        s->zs[0][jg] = zj;
        float z1 = __shfl_down_sync(0xffffffffu, zj, 1);
        float z2 = __shfl_down_sync(0xffffffffu, zj, 2);
        float z3 = __shfl_down_sync(0xffffffffu, zj, 3);
        if ((lane & 3) == 0) {
            st_rem_v4(mapa_u32(zs0_base + 4u * jg, peer),
                      make_float4(zj, z1, z2, z3));
            mbar_arrive_remote(mbz_rem);
        }
    }
    __syncthreads();

    for (int i = 0; i < TT; ++i) {
        const unsigned par = i & 1u;
        const unsigned nxt = par ^ 1u;

        // ---- B: wait z-base halves; add ptr@Wk (smem bcast); LSTM gates -----
        mbar_wait_parity(mbz_local, par);   // peer half (arrived ~1 iter ago)
        if (tid < HH) {
            float p0 = s->pbuf[0], p1 = s->pbuf[1];
            const float* zb = s->zs[par];
            float zi = zb[tid];
            float zf = zb[HH + tid];
            float zg = zb[2 * HH + tid];
            float zo = zb[3 * HH + tid];
            zi = fmaf(p0, s->Wks[tid],          fmaf(p1, s->Wks[H4 + tid],          zi));
            zf = fmaf(p0, s->Wks[HH + tid],     fmaf(p1, s->Wks[H4 + HH + tid],     zf));
            zg = fmaf(p0, s->Wks[2 * HH + tid], fmaf(p1, s->Wks[H4 + 2 * HH + tid], zg));
            zo = fmaf(p0, s->Wks[3 * HH + tid], fmaf(p1, s->Wks[H4 + 3 * HH + tid], zo));
            float ig = sigm_(zi);
            float fg = sigm_(zf);
            float gg = tanh_(zg);
            float og = sigm_(zo);
            float cn = fmaf(fg, s->cs[tid], ig * gg);
            s->cs[tid] = cn;
            s->hs[tid] = og * tanh_(cn);
        }
        __syncthreads();                              // b1: hs visible

        // ---- C: a-partials = h @ W2 (4 independent accumulators) -----------
        {
            const int q = tid >> 7, j = tid & 127;
            const float* w2 = s->W2s + q * 32 * HH + j;
            const float* hp = s->hs + q * 32;
            float a0 = 0.f, a1 = 0.f, a2 = 0.f, a3 = 0.f;
            #pragma unroll
            for (int k = 0; k < 32; k += 4) {
                a0 = fmaf(hp[k],     w2[k * HH],       a0);
                a1 = fmaf(hp[k + 1], w2[(k + 1) * HH], a1);
                a2 = fmaf(hp[k + 2], w2[(k + 2) * HH], a2);
                a3 = fmaf(hp[k + 3], w2[(k + 3) * HH], a3);
            }
            s->ap[q * HH + j] = (a0 + a1) + (a2 + a3);
        }
        __syncthreads();                              // b2: ap visible

        // ---- D fused with A(i+1): aa-fold + scores + next-step z-partials --
        {
            // fold the 4 k-quarter partials into this lane's a-quad
            const float4* apq = (const float4*)s->ap;
            float4 q0 = apq[lane], q1 = apq[32 + lane],
                   q2 = apq[64 + lane], q3 = apq[96 + lane];
            float4 a4;
            a4.x = (q0.x + q1.x) + (q2.x + q3.x);
            a4.y = (q0.y + q1.y) + (q2.y + q3.y);
            a4.z = (q0.z + q1.z) + (q2.z + q3.z);
            a4.w = (q0.w + q1.w) + (q2.w + q3.w);

            // h_i slice via 4 vector loads
            const float4* h4 = ((const float4*)s->hs) + kq * 4;
            float4 hv0 = h4[0], hv1 = h4[1], hv2 = h4[2], hv3 = h4[3];
            float hreg[16] = {hv0.x, hv0.y, hv0.z, hv0.w,
                              hv1.x, hv1.y, hv1.z, hv1.w,
                              hv2.x, hv2.y, hv2.z, hv2.w,
                              hv3.x, hv3.y, hv3.z, hv3.w};
            float4 buf[8];
            #pragma unroll
            for (int k = 0; k < 8; ++k)
                buf[k] = *(const float4*)(WrB + (size_t)k * H4);
            float4 az = make_float4(0.f, 0.f, 0.f, 0.f);
            #pragma unroll
            for (int it = 0; it < 8; ++it) {
                float4 wN = *(const float4*)(WrB + (size_t)(8 + it) * H4);
                az.x = fmaf(hreg[it], buf[it].x, az.x);
                az.y = fmaf(hreg[it], buf[it].y, az.y);
                az.z = fmaf(hreg[it], buf[it].z, az.z);
                az.w = fmaf(hreg[it], buf[it].w, az.w);
                int tl = warp + it * 16;
                float4 p = ((const float4*)(s->ep + tl * HH))[lane];
                float sv;
                sv = Vr.x * tanh_(p.x + a4.x);
                sv = fmaf(Vr.y, tanh_(p.y + a4.y), sv);
                sv = fmaf(Vr.z, tanh_(p.z + a4.z), sv);
                sv = fmaf(Vr.w, tanh_(p.w + a4.w), sv);
                sv += __shfl_xor_sync(0xffffffffu, sv, 16);
                sv += __shfl_xor_sync(0xffffffffu, sv, 8);
                sv += __shfl_xor_sync(0xffffffffu, sv, 4);
                sv += __shfl_xor_sync(0xffffffffu, sv, 2);
                sv += __shfl_xor_sync(0xffffffffu, sv, 1);
                if (lane == 0) s->sc[tl] = sv;
                az.x = fmaf(hreg[8 + it], wN.x, az.x);
                az.y = fmaf(hreg[8 + it], wN.y, az.y);
                az.z = fmaf(hreg[8 + it], wN.z, az.z);
                az.w = fmaf(hreg[8 + it], wN.w, az.w);
            }
            ((float4*)(s->zp + kq * HZ))[j4] = az;   // z partials for step i+1
        }
        __syncthreads();                              // b3: sc, zp visible

        // ---- E (warp 0 ONLY) CONCURRENT with A2' (warps 4-11) --------------
        if (warp == 0) {
            // 4 rows per lane: sc[4*lane .. 4*lane+3], one LDS.128
            float4 sq = ((const float4*)s->sc)[lane];
            float e0 = ex2f_(sq.x * L2E);
            float e1 = ex2f_(sq.y * L2E);
            float e2 = ex2f_(sq.z * L2E);
            float e3 = ex2f_(sq.w * L2E);
            float se = (e0 + e1) + (e2 + e3);
            // local fold with first-index tiebreak (ascending, strict >)
            float vm = sq.x; int im = 0;
            if (sq.y > vm) { vm = sq.y; im = 1; }
            if (sq.z > vm) { vm = sq.z; im = 2; }
            if (sq.w > vm) { vm = sq.w; im = 3; }
            int ig = (int)rank * HT + 4 * lane + im;   // global row index
            // 5-stage butterfly carrying (max, idx, sum)
            #pragma unroll
            for (int off = 16; off; off >>= 1) {
                float v2 = __shfl_xor_sync(0xffffffffu, vm, off);
                int   i2 = __shfl_xor_sync(0xffffffffu, ig, off);
                se      += __shfl_xor_sync(0xffffffffu, se, off);
                if (v2 > vm || (v2 == vm && i2 < ig)) { vm = v2; ig = i2; }
            }
            // send our triple to peer (lane 0)
            if (lane == 0) {
                unsigned exr = par ? ex_rem1 : ex_rem0;
                st_rem_f32(exr + 0u, vm);
                st_rem_f32(exr + 4u, __int_as_float(ig));
                st_rem_f32(exr + 8u, se);
                mbar_arrive_remote(mbs_rem);
            }
            // wait for peer triple, combine (all lanes redundantly)
            mbar_wait_parity(mbs_local, par);
            const float* ex = s->exch[par];
            float pm = ex[0];
            int   pi = __float_as_int(ex[1]);
            float pS = ex[2];
            bool  tp = (pm > vm) || (pm == vm && pi < ig);
            int   gi = tp ? pi : ig;
            float St = se + pS;
            float kE0 = rcpf_(St);
            kE0 = kE0 * (2.0f - St * kE0);            // NR step -> full fp32 acc
            if (lane == 0) {
                s->pbuf[0] = s->xs[gi * 2];
                s->pbuf[1] = s->xs[gi * 2 + 1];
            }
            // output: 4 contiguous rows per lane as one STG.128
            float4 ov = make_float4(e0 * kE0, e1 * kE0, e2 * kE0, e3 * kE0);
            *(float4*)(out + ((size_t)b * TT + i) * TT + rank * HT + 4 * lane) = ov;
        } else if (warp >= 4 && warp < 12) {
            // A2': reduce zp_{i+1} + b; exchange z-base (warps 4-11)
            int zt = tid - 128;                       // 0..255
            int jg = rank * HZ + zt;
            float zj = s->zp[zt]          + s->zp[HZ + zt]
                     + s->zp[2 * HZ + zt] + s->zp[3 * HZ + zt]
                     + s->zp[4 * HZ + zt] + s->zp[5 * HZ + zt]
                     + s->zp[6 * HZ + zt] + s->zp[7 * HZ + zt];
            zj += s->bs[jg];
            s->zs[nxt][jg] = zj;
            float z1 = __shfl_down_sync(0xffffffffu, zj, 1);
            float z2 = __shfl_down_sync(0xffffffffu, zj, 2);
            float z3 = __shfl_down_sync(0xffffffffu, zj, 3);
            if ((lane & 3) == 0) {
                unsigned zb = (nxt ? zs1_base : zs0_base) + 4u * jg;
                st_rem_v4(mapa_u32(zb, peer), make_float4(zj, z1, z2, z3));
                mbar_arrive_remote(mbz_rem);
            }
        }
        if (warp < 4)  bar_sync_(6, 128);             // pbuf -> warps 0-3
        if (warp < 12) bar_sync_(7, 384);             // zs[nxt] -> warps 0-3
        // Warps 12-15 skip E/A2'/bar6/bar7; max skew 1 iter, blocked at b1.
        // WAR safety: sc read by warp 0 completes before its b1_{i+1} (program
        // order), and sc writers (D_{i+1}) sit behind b2_{i+1} (full barrier).
        // pbuf: read in B_i, rewritten in E_i (after b3_i > b1_i). zs/exch
        // double-buffered by parity with the send->peer-combine->peer-b1
        // transitive chain; zp gated by b2/b3 (unchanged from R9).
    }
    CLUSTER_SYNC_();   // keep SMEM alive until peer's remote ops are done
}

// ---------------- launch ----------------------------------------------------
extern "C" void kernel_launch(void* const* d_in, const int* in_sizes, int n_in,
                              void* d_out, int out_size) {
    const float* x   = (const float*)d_in[0];
    const float* enc = (const float*)d_in[1];
    const float* h0  = (const float*)d_in[2];
    const float* c0  = (const float*)d_in[3];
    const float* W1  = (const float*)d_in[4];
    const float* W2  = (const float*)d_in[5];
    const float* V   = (const float*)d_in[6];
    const float* Wk  = (const float*)d_in[7];
    const float* Wr  = (const float*)d_in[8];
    const float* bia = (const float*)d_in[9];
    float* out = (float*)d_out;

    const int enc_smem = (HH * HH + 32 * HH) * (int)sizeof(float);  // 80 KB
    cudaFuncSetAttribute(encproj_k, cudaFuncAttributeMaxDynamicSharedMemorySize,
                         enc_smem);
    cudaFuncSetAttribute(decode_k, cudaFuncAttributeMaxDynamicSharedMemorySize,
                         (int)sizeof(DecodeSmem));

    encproj_k<<<(BB * TT) / 32, 128, enc_smem>>>(enc, W1);
    decode_k<<<BB * 2, 512, sizeof(DecodeSmem)>>>(x, h0, c0, W2, V, Wk, Wr, bia, out);
}

// round 14
// speedup vs baseline: 1.1248x; 1.0357x over previous
#include <cuda_runtime.h>

#define BB 64
#define TT 256
#define HH 128
#define H4 512
#define HT 128   // t-half handled per CTA
#define HZ 256   // z-half handled per CTA
#define L2E 1.4426950408889634f

// Precomputed enc_proj = enc_output @ W1, [B*T, H]  (8 MB scratch)
__device__ float g_ep[BB * TT * HH];

// ---------------- fast-but-accurate transcendentals (err ~5e-7 abs) --------
__device__ __forceinline__ float ex2f_(float x) {
    float y; asm("ex2.approx.ftz.f32 %0, %1;" : "=f"(y) : "f"(x)); return y;
}
__device__ __forceinline__ float rcpf_(float x) {
    float y; asm("rcp.approx.ftz.f32 %0, %1;" : "=f"(y) : "f"(x)); return y;
}
__device__ __forceinline__ float tanh_(float x) {
    float ax = fabsf(x);
    float e  = ex2f_(ax * 2.8853900817779268f);   // 2*log2(e)
    float y  = fmaf(-2.0f, rcpf_(e + 1.0f), 1.0f);
    return copysignf(y, x);
}
__device__ __forceinline__ float sigm_(float x) {
    return rcpf_(1.0f + ex2f_(-L2E * x));
}

// ---------------- DSMEM / mbarrier helpers ---------------------------------
__device__ __forceinline__ unsigned smem_u32(const void* p) {
    unsigned a;
    asm("{ .reg .u64 t; cvta.to.shared.u64 t, %1; cvt.u32.u64 %0, t; }"
        : "=r"(a) : "l"(p));
    return a;
}
__device__ __forceinline__ unsigned mapa_u32(unsigned a, unsigned rank) {
    unsigned o; asm("mapa.shared::cluster.u32 %0, %1, %2;" : "=r"(o) : "r"(a), "r"(rank));
    return o;
}
__device__ __forceinline__ void st_rem_f32(unsigned a, float v) {
    asm volatile("st.shared::cluster.f32 [%0], %1;" :: "r"(a), "f"(v) : "memory");
}
__device__ __forceinline__ void st_rem_v4(unsigned a, float4 v) {
    asm volatile("st.shared::cluster.v4.f32 [%0], {%1, %2, %3, %4};"
                 :: "r"(a), "f"(v.x), "f"(v.y), "f"(v.z), "f"(v.w) : "memory");
}
__device__ __forceinline__ void mbar_init(unsigned a, unsigned cnt) {
    asm volatile("mbarrier.init.shared.b64 [%0], %1;" :: "r"(a), "r"(cnt) : "memory");
}
__device__ __forceinline__ void mbar_arrive_remote(unsigned a) {
    asm volatile("mbarrier.arrive.release.cluster.shared::cluster.b64 _, [%0];"
                 :: "r"(a) : "memory");
}
__device__ __forceinline__ void mbar_wait_parity(unsigned a, unsigned par) {
    unsigned done;
    do {
        asm volatile(
            "{ .reg .pred p;\n\t"
            "mbarrier.try_wait.parity.acquire.cluster.shared::cta.b64 p, [%1], %2, 0x989680;\n\t"
            "selp.b32 %0, 1, 0, p; }"
            : "=r"(done) : "r"(a), "r"(par) : "memory");
    } while (!done);
}
__device__ __forceinline__ void bar_sync_(int id, int cnt) {
    asm volatile("bar.sync %0, %1;" :: "r"(id), "r"(cnt) : "memory");
}
#define CLUSTER_SYNC_() do { \
    asm volatile("barrier.cluster.arrive.aligned;" ::: "memory"); \
    asm volatile("barrier.cluster.wait.aligned;"   ::: "memory"); \
} while (0)

// quad swizzle: logical quad q (0..31) -> physical slot (conflict-free D reads)
#define QSW(q) ((((q) & 3) << 3) | ((q) >> 2))

// ---------------- kernel 1: enc_proj = enc_output @ W1 ---------------------
__global__ void __launch_bounds__(128) encproj_k(const float* __restrict__ enc,
                                                 const float* __restrict__ W1) {
    extern __shared__ float sm[];
    float* W1s = sm;                 // 128*128
    float* rb  = sm + HH * HH;       // 32*128
    int base = blockIdx.x * 32;
    {
        const float4* s4 = (const float4*)W1;
        float4* d4 = (float4*)W1s;
        for (int i = threadIdx.x; i < HH * HH / 4; i += 128) d4[i] = s4[i];
        const float4* r4 = (const float4*)(enc + (size_t)base * HH);
        float4* rd = (float4*)rb;
        for (int i = threadIdx.x; i < 32 * HH / 4; i += 128) rd[i] = r4[i];
    }
    __syncthreads();
    int j = threadIdx.x;
    for (int r0 = 0; r0 < 32; r0 += 8) {
        float acc[8] = {0.f, 0.f, 0.f, 0.f, 0.f, 0.f, 0.f, 0.f};
        #pragma unroll 8
        for (int k = 0; k < HH; ++k) {
            float w = W1s[k * HH + j];
            #pragma unroll
            for (int rr = 0; rr < 8; ++rr)
                acc[rr] = fmaf(rb[(r0 + rr) * HH + k], w, acc[rr]);
        }
        #pragma unroll
        for (int rr = 0; rr < 8; ++rr)
            g_ep[(size_t)(base + r0 + rr) * HH + j] = acc[rr];
    }
}

// ---------------- kernel 2: 2-CTA-cluster decoder --------------------------
struct DecodeSmem {
    unsigned long long mb_z;     // z-base halves ready (64 remote arrives/phase)
    unsigned long long mb_s;     // peer's E-triple ready (1 arrive/phase)
    float ep[HT * HH];    // 64 KB: t-half of enc_proj, quad-swizzled rows
    float W2s[HH * HH];   // 64 KB
    float Wks[2 * H4];    //  4 KB
    float bs[H4];
    float Vsw[HH];        //  V, quad-swizzled
    float xs[TT * 2];
    float hs[HH];
    float cs[HH];
    float zp[8 * HZ];     //  8 KB: k-partials for this CTA's z-half
    float zs[2][H4];      //  double-buffered z-base (h@Wr + b), both halves
    float ap[4 * HH];     //  C k-quarter partials
    float aawb[16 * HH];  //  8 KB: per-warp folded aa, quad-swizzled
    float sc[HT];         //  our half of the scores only
    float exch[2][4];     //  peer writes (m, idx-bits, S) here, by parity
    float pbuf[2];        //  ptr broadcast (written by warp 0 lane 0)
};

__global__ void __launch_bounds__(512, 1) __cluster_dims__(2, 1, 1)
decode_k(const float* __restrict__ x,   const float* __restrict__ h0,
         const float* __restrict__ c0,  const float* __restrict__ W2,
         const float* __restrict__ V,   const float* __restrict__ Wk,
         const float* __restrict__ Wr,  const float* __restrict__ bias,
         float* __restrict__ out)
{
    extern __shared__ float smraw[];
    DecodeSmem* s = (DecodeSmem*)smraw;

    const int b    = blockIdx.x >> 1;
    unsigned rank; asm("mov.u32 %0, %%cluster_ctarank;" : "=r"(rank));
    const unsigned peer = rank ^ 1u;
    const int tid  = threadIdx.x;
    const int lane = tid & 31;
    const int warp = tid >> 5;

    // ---- prologue: stage reusable data into SMEM ---------------------------
    {
        // ep: coalesced gmem read, quad-swizzled smem write
        const float4* epsrc = (const float4*)(g_ep + ((size_t)b * TT + rank * HT) * HH);
        float4* epdst = (float4*)s->ep;
        for (int i = tid; i < HT * 32; i += 512) {
            int row = i >> 5, q = i & 31;
            epdst[row * 32 + QSW(q)] = epsrc[row * 32 + q];
        }

        const float4* w2src = (const float4*)W2;
        float4* w2dst = (float4*)s->W2s;
        for (int i = tid; i < HH * HH / 4; i += 512) w2dst[i] = w2src[i];

        if (tid < 2 * H4 / 4) ((float4*)s->Wks)[tid] = ((const float4*)Wk)[tid];
        if (tid < H4 / 4)     ((float4*)s->bs)[tid]  = ((const float4*)bias)[tid];
        if (tid < HH / 4)     ((float4*)s->Vsw)[QSW(tid)] = ((const float4*)V)[tid];
        if (tid < TT * 2 / 4) ((float4*)s->xs)[tid]  = ((const float4*)(x + (size_t)b * TT * 2))[tid];
        if (tid < HH / 4)     ((float4*)s->hs)[tid]  = ((const float4*)(h0 + (size_t)b * HH))[tid];
        if (tid < HH / 4)     ((float4*)s->cs)[tid]  = ((const float4*)(c0 + (size_t)b * HH))[tid];
        if (tid == 0) {
            s->pbuf[0] = 1.0f; s->pbuf[1] = 1.0f;
            mbar_init(smem_u32(&s->mb_z), 64);   // 64 v4 remote arrives per phase
            mbar_init(smem_u32(&s->mb_s), 1);    // 1 triple arrive per phase
        }
    }
    __syncthreads();
    CLUSTER_SYNC_();   // peer barriers initialized before any remote arrive

    const unsigned mbz_local = smem_u32(&s->mb_z);
    const unsigned mbs_local = smem_u32(&s->mb_s);
    const unsigned mbz_rem   = mapa_u32(mbz_local, peer);
    const unsigned mbs_rem   = mapa_u32(mbs_local, peer);
    const unsigned zs0_base  = smem_u32(s->zs[0]);
    const unsigned zs1_base  = smem_u32(s->zs[1]);
    const unsigned ex_rem0   = mapa_u32(smem_u32(s->exch[0]), peer);
    const unsigned ex_rem1   = mapa_u32(smem_u32(s->exch[1]), peer);

    // A-role layout: kq = k-eighth (0..7), j4 = output quad within our z-half
    const int kq = tid >> 6;
    const int j4 = tid & 63;
    const float* WrB = Wr + (size_t)kq * 16 * H4 + rank * HZ + j4 * 4;

    // D-role layout: g = row-group (0..3), c8 = 16-col chunk (0..7)
    const int g  = lane >> 3;
    const int c8 = lane & 7;

    // ---- prologue: zp_0 from h0, then reduce+exchange z-base (parity 0) ----
    {
        const float* hp = s->hs + kq * 16;
        const float* wp = WrB;
        float4 az = make_float4(0.f, 0.f, 0.f, 0.f);
        #pragma unroll
        for (int k = 0; k < 16; ++k) {
            float hk = hp[k];
            float4 w = *(const float4*)wp;
            wp += H4;
            az.x = fmaf(hk, w.x, az.x);
            az.y = fmaf(hk, w.y, az.y);
            az.z = fmaf(hk, w.z, az.z);
            az.w = fmaf(hk, w.w, az.w);
        }
        ((float4*)(s->zp + kq * HZ))[j4] = az;
    }
    __syncthreads();
    if (tid < HZ) {
        int jg = rank * HZ + tid;
        float zj = s->zp[tid]          + s->zp[HZ + tid]
                 + s->zp[2 * HZ + tid] + s->zp[3 * HZ + tid]
                 + s->zp[4 * HZ + tid] + s->zp[5 * HZ + tid]
                 + s->zp[6 * HZ + tid] + s->zp[7 * HZ + tid];
        zj += s->bs[jg];
        s->zs[0][jg] = zj;
        float z1 = __shfl_down_sync(0xffffffffu, zj, 1);
        float z2 = __shfl_down_sync(0xffffffffu, zj, 2);
        float z3 = __shfl_down_sync(0xffffffffu, zj, 3);
        if ((lane & 3) == 0) {
            st_rem_v4(mapa_u32(zs0_base + 4u * jg, peer),
                      make_float4(zj, z1, z2, z3));
            mbar_arrive_remote(mbz_rem);
        }
    }
    __syncthreads();

    for (int i = 0; i < TT; ++i) {
        const unsigned par = i & 1u;
        const unsigned nxt = par ^ 1u;

        // ---- B: wait z-base halves; add ptr@Wk (smem bcast); LSTM gates -----
        mbar_wait_parity(mbz_local, par);   // peer half (arrived ~1 iter ago)
        if (tid < HH) {
            float p0 = s->pbuf[0], p1 = s->pbuf[1];
            const float* zb = s->zs[par];
            float zi = zb[tid];
            float zf = zb[HH + tid];
            float zg = zb[2 * HH + tid];
            float zo = zb[3 * HH + tid];
            zi = fmaf(p0, s->Wks[tid],          fmaf(p1, s->Wks[H4 + tid],          zi));
            zf = fmaf(p0, s->Wks[HH + tid],     fmaf(p1, s->Wks[H4 + HH + tid],     zf));
            zg = fmaf(p0, s->Wks[2 * HH + tid], fmaf(p1, s->Wks[H4 + 2 * HH + tid], zg));
            zo = fmaf(p0, s->Wks[3 * HH + tid], fmaf(p1, s->Wks[H4 + 3 * HH + tid], zo));
            float ig = sigm_(zi);
            float fg = sigm_(zf);
            float gg = tanh_(zg);
            float og = sigm_(zo);
            float cn = fmaf(fg, s->cs[tid], ig * gg);
            s->cs[tid] = cn;
            s->hs[tid] = og * tanh_(cn);
        }
        __syncthreads();                              // b1: hs visible

        // ---- C: a-partials = h @ W2 (4 independent accumulators) -----------
        {
            const int q = tid >> 7, j = tid & 127;
            const float* w2 = s->W2s + q * 32 * HH + j;
            const float* hp = s->hs + q * 32;
            float a0 = 0.f, a1 = 0.f, a2 = 0.f, a3 = 0.f;
            #pragma unroll
            for (int k = 0; k < 32; k += 4) {
                a0 = fmaf(hp[k],     w2[k * HH],       a0);
                a1 = fmaf(hp[k + 1], w2[(k + 1) * HH], a1);
                a2 = fmaf(hp[k + 2], w2[(k + 2) * HH], a2);
                a3 = fmaf(hp[k + 3], w2[(k + 3) * HH], a3);
            }
            s->ap[q * HH + j] = (a0 + a1) + (a2 + a3);
        }
        __syncthreads();                              // b2: ap visible

        // ---- D fused with A(i+1): 4-rows/8-lanes scheme (6 SHFLs/lane) -----
        {
            // per-warp aa fold into quad-swizzled warp-private buffer
            const float4* apq = (const float4*)s->ap;
            float4 q0 = apq[lane], q1 = apq[32 + lane],
                   q2 = apq[64 + lane], q3 = apq[96 + lane];
            float4 a4;
            a4.x = (q0.x + q1.x) + (q2.x + q3.x);
            a4.y = (q0.y + q1.y) + (q2.y + q3.y);
            a4.z = (q0.z + q1.z) + (q2.z + q3.z);
            a4.w = (q0.w + q1.w) + (q2.w + q3.w);
            ((float4*)s->aawb)[warp * 32 + QSW(lane)] = a4;
            __syncwarp();

            // h_i slice via 4 vector loads
            const float4* h4 = ((const float4*)s->hs) + kq * 4;
            float4 hv0 = h4[0], hv1 = h4[1], hv2 = h4[2], hv3 = h4[3];
            float hreg[16] = {hv0.x, hv0.y, hv0.z, hv0.w,
                              hv1.x, hv1.y, hv1.z, hv1.w,
                              hv2.x, hv2.y, hv2.z, hv2.w,
                              hv3.x, hv3.y, hv3.z, hv3.w};
            const float4* aaw = ((const float4*)s->aawb) + warp * 32;
            const float4* vsw = (const float4*)s->Vsw;
            const float4* epb = (const float4*)s->ep;
            float4 az = make_float4(0.f, 0.f, 0.f, 0.f);

            #pragma unroll
            for (int p = 0; p < 2; ++p) {
                const int row = warp * 8 + p * 4 + g;
                float acc0 = 0.f, acc1 = 0.f;
                #pragma unroll
                for (int j = 0; j < 4; ++j) {
                    const int k = p * 8 + j * 2;
                    // Wr loads issued early; consumed after the MUFU block
                    float4 w0 = *(const float4*)(WrB + (size_t)k * H4);
                    float4 w1 = *(const float4*)(WrB + (size_t)(k + 1) * H4);
                    const int pq_i = j * 8 + c8;      // physical (swizzled) quad
                    float4 pq = epb[row * 32 + pq_i];
                    float4 aq = aaw[pq_i];
                    float4 vq = vsw[pq_i];
                    acc0 = fmaf(vq.x, tanh_(pq.x + aq.x), acc0);
                    acc1 = fmaf(vq.y, tanh_(pq.y + aq.y), acc1);
                    acc0 = fmaf(vq.z, tanh_(pq.z + aq.z), acc0);
                    acc1 = fmaf(vq.w, tanh_(pq.w + aq.w), acc1);
                    az.x = fmaf(hreg[k],     w0.x, az.x);
                    az.y = fmaf(hreg[k],     w0.y, az.y);
                    az.z = fmaf(hreg[k],     w0.z, az.z);
                    az.w = fmaf(hreg[k],     w0.w, az.w);
                    az.x = fmaf(hreg[k + 1], w1.x, az.x);
                    az.y = fmaf(hreg[k + 1], w1.y, az.y);
                    az.z = fmaf(hreg[k + 1], w1.z, az.z);
                    az.w = fmaf(hreg[k + 1], w1.w, az.w);
                }
                float acc = acc0 + acc1;
                acc += __shfl_xor_sync(0xffffffffu, acc, 1);
                acc += __shfl_xor_sync(0xffffffffu, acc, 2);
                acc += __shfl_xor_sync(0xffffffffu, acc, 4);
                if (c8 == 0) s->sc[row] = acc;
            }
            ((float4*)(s->zp + kq * HZ))[j4] = az;   // z partials for step i+1
        }
        __syncthreads();                              // b3: sc, zp visible

        // ---- E (warp 0 ONLY) CONCURRENT with A2' (warps 4-11) --------------
        if (warp == 0) {
            // 4 rows per lane: sc[4*lane .. 4*lane+3], one LDS.128
            float4 sq = ((const float4*)s->sc)[lane];
            float e0 = ex2f_(sq.x * L2E);
            float e1 = ex2f_(sq.y * L2E);
            float e2 = ex2f_(sq.z * L2E);
            float e3 = ex2f_(sq.w * L2E);
            float se = (e0 + e1) + (e2 + e3);
            // local fold with first-index tiebreak (ascending, strict >)
            float vm = sq.x; int im = 0;
            if (sq.y > vm) { vm = sq.y; im = 1; }
            if (sq.z > vm) { vm = sq.z; im = 2; }
            if (sq.w > vm) { vm = sq.w; im = 3; }
            int ig = (int)rank * HT + 4 * lane + im;   // global row index
            // 5-stage butterfly carrying (max, idx, sum)
            #pragma unroll
            for (int off = 16; off; off >>= 1) {
                float v2 = __shfl_xor_sync(0xffffffffu, vm, off);
                int   i2 = __shfl_xor_sync(0xffffffffu, ig, off);
                se      += __shfl_xor_sync(0xffffffffu, se, off);
                if (v2 > vm || (v2 == vm && i2 < ig)) { vm = v2; ig = i2; }
            }
            // send our triple to peer (lane 0)
            if (lane == 0) {
                unsigned exr = par ? ex_rem1 : ex_rem0;
                st_rem_f32(exr + 0u, vm);
                st_rem_f32(exr + 4u, __int_as_float(ig));
                st_rem_f32(exr + 8u, se);
                mbar_arrive_remote(mbs_rem);
            }
            // wait for peer triple, combine (all lanes redundantly)
            mbar_wait_parity(mbs_local, par);
            const float* ex = s->exch[par];
            float pm = ex[0];
            int   pi = __float_as_int(ex[1]);
            float pS = ex[2];
            bool  tp = (pm > vm) || (pm == vm && pi < ig);
            int   gi = tp ? pi : ig;
            float St = se + pS;
            float kE0 = rcpf_(St);
            kE0 = kE0 * (2.0f - St * kE0);            // NR step -> full fp32 acc
            if (lane == 0) {
                s->pbuf[0] = s->xs[gi * 2];
                s->pbuf[1] = s->xs[gi * 2 + 1];
            }
            // output: 4 contiguous rows per lane as one STG.128
            float4 ov = make_float4(e0 * kE0, e1 * kE0, e2 * kE0, e3 * kE0);
            *(float4*)(out + ((size_t)b * TT + i) * TT + rank * HT + 4 * lane) = ov;
        } else if (warp >= 4 && warp < 12) {
            // A2': reduce zp_{i+1} + b; exchange z-base (warps 4-11)
            int zt = tid - 128;                       // 0..255
            int jg = rank * HZ + zt;
            float zj = s->zp[zt]          + s->zp[HZ + zt]
                     + s->zp[2 * HZ + zt] + s->zp[3 * HZ + zt]
                     + s->zp[4 * HZ + zt] + s->zp[5 * HZ + zt]
                     + s->zp[6 * HZ + zt] + s->zp[7 * HZ + zt];
            zj += s->bs[jg];
            s->zs[nxt][jg] = zj;
            float z1 = __shfl_down_sync(0xffffffffu, zj, 1);
            float z2 = __shfl_down_sync(0xffffffffu, zj, 2);
            float z3 = __shfl_down_sync(0xffffffffu, zj, 3);
            if ((lane & 3) == 0) {
                unsigned zb = (nxt ? zs1_base : zs0_base) + 4u * jg;
                st_rem_v4(mapa_u32(zb, peer), make_float4(zj, z1, z2, z3));
                mbar_arrive_remote(mbz_rem);
            }
        }
        if (warp < 4)  bar_sync_(6, 128);             // pbuf -> warps 0-3
        if (warp < 12) bar_sync_(7, 384);             // zs[nxt] -> warps 0-3
        // Warps 12-15 skip E/A2'/bar6/bar7; max skew 1 iter, blocked at b1.
        // WAR safety: sc read by warp 0 completes before its b1_{i+1} (program
        // order), and sc writers (D_{i+1}) sit behind b2_{i+1} (full barrier).
        // aawb is warp-private, gated by __syncwarp + b2. pbuf: read in B_i,
        // rewritten in E_i (after b3_i > b1_i). zs/exch double-buffered by
        // parity with the send->peer-combine->peer-b1 transitive chain; zp
        // gated by b2/b3 (unchanged from R12).
    }
    CLUSTER_SYNC_();   // keep SMEM alive until peer's remote ops are done
}

// ---------------- launch ----------------------------------------------------
extern "C" void kernel_launch(void* const* d_in, const int* in_sizes, int n_in,
                              void* d_out, int out_size) {
    const float* x   = (const float*)d_in[0];
    const float* enc = (const float*)d_in[1];
    const float* h0  = (const float*)d_in[2];
    const float* c0  = (const float*)d_in[3];
    const float* W1  = (const float*)d_in[4];
    const float* W2  = (const float*)d_in[5];
    const float* V   = (const float*)d_in[6];
    const float* Wk  = (const float*)d_in[7];
    const float* Wr  = (const float*)d_in[8];
    const float* bia = (const float*)d_in[9];
    float* out = (float*)d_out;

    const int enc_smem = (HH * HH + 32 * HH) * (int)sizeof(float);  // 80 KB
    cudaFuncSetAttribute(encproj_k, cudaFuncAttributeMaxDynamicSharedMemorySize,
                         enc_smem);
    cudaFuncSetAttribute(decode_k, cudaFuncAttributeMaxDynamicSharedMemorySize,
                         (int)sizeof(DecodeSmem));

    encproj_k<<<(BB * TT) / 32, 128, enc_smem>>>(enc, W1);
    decode_k<<<BB * 2, 512, sizeof(DecodeSmem)>>>(x, h0, c0, W2, V, Wk, Wr, bia, out);
}